// round 11
// baseline (speedup 1.0000x reference)
#include <cuda_runtime.h>
#include <math.h>

#define NTOK 8192
#define HDIM 4096
#define NOUT 12       // M_ANCH * (D+1)
#define NANCH 4
#define KOUT 16

// GEMM decomposition (rounding-order-mandated): 2 contiguous chunks of 2048.
#define KC 2048
#define HT 32                       // k per tile
#define NT (KC / HT)                // 64 tiles
#define TOKB 128                    // tokens per block
#define TPB 128
#define NSTAGE 4
#define WPAIR_BYTES 16384           // one [2048][2] col-pair plane
#define W_BYTES (6 * WPAIR_BYTES)   // 98304
#define TILE_BYTES (TOKB * HT * 4)  // 16384: 8 planes x 128 tok x 16B
#define SMEM_TOTAL (W_BYTES + NSTAGE * TILE_BYTES)   // 163840

extern "C" __device__ float __nv_expf(float);

// chunk partial sums: g_part[chunk][token][j]
__device__ float g_part[2][NTOK][NOUT];

// ---------------------------------------------------------------------------
// XLA f32 tanh (EmitFastTanh), bit-exact — frozen since round 5.
// ---------------------------------------------------------------------------
__device__ __forceinline__ float xla_tanhf(float x) {
    const float plus_clamp = 7.90531110763549805f;
    const float ax = fabsf(x);
    const float xc = fmaxf(fminf(x, plus_clamp), -plus_clamp);
    const float x2 = __fmul_rn(xc, xc);
    float p = fmaf(x2, -2.76076847742355e-16f, 2.00018790482477e-13f);
    p = fmaf(x2, p, -8.60467152213735e-11f);
    p = fmaf(x2, p, 5.12229709037114e-08f);
    p = fmaf(x2, p, 1.48572235717979e-05f);
    p = fmaf(x2, p, 6.37261928875436e-04f);
    p = fmaf(x2, p, 4.89352455891786e-03f);
    p = __fmul_rn(xc, p);
    float q = fmaf(x2, 1.19825839466702e-06f, 1.18534705686654e-04f);
    q = fmaf(x2, q, 2.26843463243900e-03f);
    q = fmaf(x2, q, 4.89352518554385e-03f);
    return (ax < 0.0004f) ? x : __fdiv_rn(p, q);
}
__device__ __forceinline__ float xla_sigmoidf(float x) {
    const float t = xla_tanhf(__fmul_rn(0.5f, x));
    return __fadd_rn(__fmul_rn(0.5f, t), 0.5f);
}

// ---------------------------------------------------------------------------
// One k, two tokens, 3 col-pairs each. Same IEEE f32x2 fma chain (bit-exact
// vs the passing kernel: per-lane independent fmaf chains, ascending k).
// ---------------------------------------------------------------------------
__device__ __forceinline__ void fma3x2(float a, float b, unsigned wk,
                                       unsigned long long& axA,
                                       unsigned long long& ayA,
                                       unsigned long long& azA,
                                       unsigned long long& axB,
                                       unsigned long long& ayB,
                                       unsigned long long& azB) {
    asm("{\n\t"
        ".reg .b64 hA, hB, w0, w1, w2;\n\t"
        "mov.b64 hA, {%6, %6};\n\t"
        "mov.b64 hB, {%7, %7};\n\t"
        "ld.shared.b64 w0, [%8];\n\t"
        "ld.shared.b64 w1, [%8+16384];\n\t"
        "ld.shared.b64 w2, [%8+32768];\n\t"
        "fma.rn.f32x2 %0, hA, w0, %0;\n\t"
        "fma.rn.f32x2 %1, hA, w1, %1;\n\t"
        "fma.rn.f32x2 %2, hA, w2, %2;\n\t"
        "fma.rn.f32x2 %3, hB, w0, %3;\n\t"
        "fma.rn.f32x2 %4, hB, w1, %4;\n\t"
        "fma.rn.f32x2 %5, hB, w2, %5;\n\t"
        "}"
        : "+l"(axA), "+l"(ayA), "+l"(azA),
          "+l"(axB), "+l"(ayB), "+l"(azB)
        : "f"(a), "f"(b), "r"(wk));
}

// ---------------------------------------------------------------------------
// Kernel 1: per-chunk partial logits. 2 tokens/thread, W in smem pair-planes,
// hidden via 16B cp.async into plane-major tiles, 4-stage pipeline.
// ---------------------------------------------------------------------------
__global__ __launch_bounds__(TPB, 1)
void logits_kernel(const float* __restrict__ hidden,
                   const float* __restrict__ W) {
    extern __shared__ char sm[];
    const int tid   = threadIdx.x;
    const int chunk = blockIdx.y;
    const int kc    = chunk * KC;
    const int tok0  = blockIdx.x * TOKB;
    const unsigned sb = (unsigned)__cvta_generic_to_shared(sm);
    const unsigned tb = sb + W_BYTES;

#define STAGE(T) do {                                                        \
    const int _t = (T);                                                      \
    const unsigned dst0 = tb + (unsigned)(_t & (NSTAGE - 1)) * TILE_BYTES;   \
    const float* src0 = hidden + (size_t)tok0 * HDIM + kc + _t * HT;         \
    _Pragma("unroll")                                                        \
    for (int r = 0; r < 8; ++r) {                                            \
        const int s = tid + r * TPB;                                         \
        const int tok = s >> 3, p = s & 7;                                   \
        const float* src = src0 + (size_t)tok * HDIM + p * 4;                \
        const unsigned dst = dst0 + p * (TOKB * 16) + tok * 16;              \
        asm volatile("cp.async.ca.shared.global [%0], [%1], 16;"             \
                     :: "r"(dst), "l"(src));                                 \
    }                                                                        \
    asm volatile("cp.async.commit_group;");                                  \
} while (0)

    STAGE(0); STAGE(1); STAGE(2);

    // W preload into pair-planes: plane q holds cols (2q, 2q+1) as [k][2].
    for (int q = 0; q < 6; ++q) {
#pragma unroll
        for (int c = 0; c < 2; ++c) {
            const float4* wg = (const float4*)(W + (size_t)(q * 2 + c) * HDIM + kc);
            float* dstf = (float*)sm + q * 4096 + c;
            for (int kq = tid; kq < 512; kq += TPB) {
                const float4 v = wg[kq];
                const int k8 = kq * 8;
                dstf[k8 + 0] = v.x;
                dstf[k8 + 2] = v.y;
                dstf[k8 + 4] = v.z;
                dstf[k8 + 6] = v.w;
            }
        }
    }

    const int jh  = tid & 1;
    const int ltA = tid >> 1;             // tokens ltA and ltA+64
    const unsigned wb  = sb + jh * (3 * WPAIR_BYTES);
    const unsigned hA0 = tb + ltA * 16;
    const unsigned hB0 = tb + (ltA + 64) * 16;

    unsigned long long ax = 0ull, ay = 0ull, az = 0ull;   // token A, pairs 0..2
    unsigned long long bx = 0ull, by = 0ull, bz = 0ull;   // token B

    for (int t = 0; t < NT; ++t) {
        if (t + 3 < NT) {
            STAGE(t + 3);
            asm volatile("cp.async.wait_group 3;");
        } else {
            const int rem = NT - 1 - t;
            if (rem == 2)      asm volatile("cp.async.wait_group 2;");
            else if (rem == 1) asm volatile("cp.async.wait_group 1;");
            else               asm volatile("cp.async.wait_group 0;");
        }
        __syncthreads();

        const unsigned tbt = (unsigned)(t & (NSTAGE - 1)) * TILE_BYTES;
        unsigned wk = wb + (unsigned)(t * HT) * 8;
#pragma unroll
        for (int p = 0; p < 8; ++p) {
            float4 hA, hB;
            asm("ld.shared.v4.f32 {%0,%1,%2,%3}, [%4];"
                : "=f"(hA.x), "=f"(hA.y), "=f"(hA.z), "=f"(hA.w)
                : "r"(hA0 + tbt + p * (TOKB * 16)));
            asm("ld.shared.v4.f32 {%0,%1,%2,%3}, [%4];"
                : "=f"(hB.x), "=f"(hB.y), "=f"(hB.z), "=f"(hB.w)
                : "r"(hB0 + tbt + p * (TOKB * 16)));
            fma3x2(hA.x, hB.x, wk,      ax, ay, az, bx, by, bz);
            fma3x2(hA.y, hB.y, wk + 8,  ax, ay, az, bx, by, bz);
            fma3x2(hA.z, hB.z, wk + 16, ax, ay, az, bx, by, bz);
            fma3x2(hA.w, hB.w, wk + 24, ax, ay, az, bx, by, bz);
            wk += 32;
        }
        __syncthreads();
    }
#undef STAGE

    const int gtA = tok0 + ltA;
    float2* pA = (float2*)&g_part[chunk][gtA][jh * 6];
    float2* pB = (float2*)&g_part[chunk][gtA + 64][jh * 6];
    pA[0] = *(float2*)&ax; pA[1] = *(float2*)&ay; pA[2] = *(float2*)&az;
    pB[0] = *(float2*)&bx; pB[1] = *(float2*)&by; pB[2] = *(float2*)&bz;
}

// ---------------------------------------------------------------------------
// Kernel 2: routing epilogue, ONE THREAD per token (<=16 nonzero cells).
// All rounding-relevant orders match the reference exactly:
//  - logit fold ((0+p0)+p1)+b
//  - per-cell scatter-add in ascending candidate order (first-occurrence fold)
//  - denominator folded in ascending cell index
//  - top-k selection on (ford(w/dn)<<32 | 63-idx), zero-fill ascending.
// ---------------------------------------------------------------------------
__device__ __forceinline__ unsigned int ford(float v) {
    unsigned int u = __float_as_uint(v);
    return (u & 0x80000000u) ? ~u : (u | 0x80000000u);
}

__global__ __launch_bounds__(64, 8)
void route_seq_kernel(const float* __restrict__ b, float* __restrict__ out) {
    const int token = blockIdx.x * 64 + threadIdx.x;

    float L[NOUT];
    {
        const float4* q0 = (const float4*)&g_part[0][token][0];
        const float4* q1 = (const float4*)&g_part[1][token][0];
#pragma unroll
        for (int v = 0; v < 3; ++v) {
            const float4 a = q0[v], c = q1[v];
            L[v*4+0] = __fadd_rn(__fadd_rn(__fadd_rn(0.f, a.x), c.x), b[v*4+0]);
            L[v*4+1] = __fadd_rn(__fadd_rn(__fadd_rn(0.f, a.y), c.y), b[v*4+1]);
            L[v*4+2] = __fadd_rn(__fadd_rn(__fadd_rn(0.f, a.z), c.z), b[v*4+2]);
            L[v*4+3] = __fadd_rn(__fadd_rn(__fadd_rn(0.f, a.w), c.w), b[v*4+3]);
        }
    }

    // anchor softmax over L[2], L[5], L[8], L[11]
    float pi[NANCH];
    {
        const float m = fmaxf(fmaxf(L[2], L[5]), fmaxf(L[8], L[11]));
        const float e0 = __nv_expf(__fadd_rn(L[2], -m));
        const float e1 = __nv_expf(__fadd_rn(L[5], -m));
        const float e2 = __nv_expf(__fadd_rn(L[8], -m));
        const float e3 = __nv_expf(__fadd_rn(L[11], -m));
        const float s = __fadd_rn(__fadd_rn(__fadd_rn(e0, e1), e2), e3);
        pi[0] = __fdiv_rn(e0, s); pi[1] = __fdiv_rn(e1, s);
        pi[2] = __fdiv_rn(e2, s); pi[3] = __fdiv_rn(e3, s);
    }

    int   ci[16];
    float cw[16];
    int m = 0;

#pragma unroll
    for (int a = 0; a < NANCH; ++a) {
        float fr[2]; int ai[2];
#pragma unroll
        for (int d = 0; d < 2; ++d) {
            const float x = L[a * 3 + d];
            float u = xla_sigmoidf(x);
            u = fminf(fmaxf(u, 1e-6f), 1.0f - 1e-6f);
            float p = __fmul_rn(u, 7.0f);
            p = fminf(p, 7.0f - 1e-6f);
            p = fmaxf(p, 0.f);
            int aa = (int)floorf(p);
            aa = max(0, min(aa, 6));
            float f = __fadd_rn(p, -(float)aa);
            f = fminf(fmaxf(f, 1e-6f), 1.0f - 1e-6f);
            fr[d] = f; ai[d] = aa;
        }
        const float om0 = __fadd_rn(1.0f, -fr[0]);
        const float om1 = __fadd_rn(1.0f, -fr[1]);
        float w[4];
        w[0] = __fmul_rn(om0,   om1);
        w[1] = __fmul_rn(fr[0], om1);
        w[2] = __fmul_rn(om0,   fr[1]);
        w[3] = __fmul_rn(fr[0], fr[1]);
        const float ws = __fadd_rn(__fadd_rn(__fadd_rn(w[0], w[1]), w[2]), w[3]);
        const float denom = __fadd_rn(ws, 1e-9f);
#pragma unroll
        for (int t = 0; t < 4; ++t) {
            const int c0 = ai[0] + (t & 1);
            const int c1 = ai[1] + ((t >> 1) & 1);
            const int idx = c0 + (c1 << 3);
            const float wv = __fmul_rn(__fdiv_rn(w[t], denom), pi[a]);
            // dedup: fold into first occurrence (ascending candidate order)
            bool found = false;
            for (int j = 0; j < m; ++j) {
                if (ci[j] == idx) { cw[j] = __fadd_rn(cw[j], wv); found = true; break; }
            }
            if (!found) { ci[m] = idx; cw[m] = wv; ++m; }
        }
    }

    // clamp (no-op for positives, kept for exactness)
    for (int j = 0; j < m; ++j) cw[j] = fmaxf(cw[j], 0.f);

    // denominator: fold live cells in ascending cell-index order (ref order)
    unsigned long long mask = 0ull;
    for (int j = 0; j < m; ++j) mask |= 1ull << ci[j];
    float s = 0.f;
    {
        unsigned long long tmp = mask;
        while (tmp) {
            const int c = __ffsll((long long)tmp) - 1;
            tmp &= tmp - 1;
            for (int j = 0; j < m; ++j)
                if (ci[j] == c) { s = __fadd_rn(s, cw[j]); break; }
        }
    }
    const float dn = __fadd_rn(s, 1e-9f);

    unsigned long long key[16];
    for (int j = 0; j < m; ++j) {
        const float wn = __fdiv_rn(cw[j], dn);
        cw[j] = wn;
        key[j] = ((unsigned long long)ford(wn) << 32) | (unsigned int)(63 - ci[j]);
    }

    float oi[KOUT], ow[KOUT];
    unsigned picked = 0;
    int r = 0;
    for (; r < m && r < KOUT; ++r) {
        int best = -1;
        unsigned long long bk = 0ull;
        for (int j = 0; j < m; ++j) {
            if ((picked >> j) & 1u) continue;
            if (best < 0 || key[j] > bk) { best = j; bk = key[j]; }
        }
        picked |= 1u << best;
        oi[r] = (float)ci[best];
        ow[r] = cw[best];
    }
    unsigned long long fill = ~mask;
    for (; r < KOUT; ++r) {
        const int c = __ffsll((long long)fill) - 1;
        fill &= fill - 1;
        oi[r] = (float)c;
        ow[r] = 0.f;
    }

    float4* out_idx = (float4*)(out + (size_t)token * KOUT);
    float4* out_w   = (float4*)(out + (size_t)NTOK * KOUT + (size_t)token * KOUT);
#pragma unroll
    for (int v = 0; v < 4; ++v) {
        out_idx[v] = make_float4(oi[v*4], oi[v*4+1], oi[v*4+2], oi[v*4+3]);
        out_w[v]   = make_float4(ow[v*4], ow[v*4+1], ow[v*4+2], ow[v*4+3]);
    }
}

// ---------------------------------------------------------------------------
extern "C" void kernel_launch(void* const* d_in, const int* in_sizes, int n_in,
                              void* d_out, int out_size) {
    const float* hidden = nullptr;
    const float* W = nullptr;
    const float* b = nullptr;
    for (int i = 0; i < n_in; ++i) {
        if (in_sizes[i] == NTOK * HDIM)      hidden = (const float*)d_in[i];
        else if (in_sizes[i] == NOUT * HDIM) W = (const float*)d_in[i];
        else if (in_sizes[i] == NOUT)        b = (const float*)d_in[i];
    }
    (void)out_size;

    cudaFuncSetAttribute(logits_kernel,
                         cudaFuncAttributeMaxDynamicSharedMemorySize, SMEM_TOTAL);
    dim3 grid(NTOK / TOKB, 2);
    logits_kernel<<<grid, TPB, SMEM_TOTAL>>>(hidden, W);
    route_seq_kernel<<<NTOK / 64, 64>>>(b, (float*)d_out);
}

// round 12
// speedup vs baseline: 1.3463x; 1.3463x over previous
#include <cuda_runtime.h>
#include <math.h>

#define NTOK 8192
#define HDIM 4096
#define NOUT 12       // M_ANCH * (D+1)
#define NANCH 4
#define KOUT 16

// GEMM decomposition (rounding-order-mandated): 2 contiguous chunks of 2048.
#define KC 2048
#define HT 32                        // k per tile
#define NT (KC / HT)                 // 64 tiles
#define TOKB 128                     // tokens per block
#define TPB 256                      // 2 threads per token
#define NSTAGE 4
#define W_BYTES (KC * 48)            // [k][12] 48B rows = 98304
#define TILE_BYTES (TOKB * HT * 4)   // 16384 (8 planes x 128 tok x 16B)
#define SMEM_TOTAL (W_BYTES + NSTAGE * TILE_BYTES)   // 163840

extern "C" __device__ float __nv_expf(float);

// chunk partial sums: g_part[chunk][token][j]
__device__ float g_part[2][NTOK][NOUT];

// ---------------------------------------------------------------------------
// XLA f32 tanh (EmitFastTanh), bit-exact — frozen since round 5.
// ---------------------------------------------------------------------------
__device__ __forceinline__ float xla_tanhf(float x) {
    const float plus_clamp = 7.90531110763549805f;
    const float ax = fabsf(x);
    const float xc = fmaxf(fminf(x, plus_clamp), -plus_clamp);
    const float x2 = __fmul_rn(xc, xc);
    float p = fmaf(x2, -2.76076847742355e-16f, 2.00018790482477e-13f);
    p = fmaf(x2, p, -8.60467152213735e-11f);
    p = fmaf(x2, p, 5.12229709037114e-08f);
    p = fmaf(x2, p, 1.48572235717979e-05f);
    p = fmaf(x2, p, 6.37261928875436e-04f);
    p = fmaf(x2, p, 4.89352455891786e-03f);
    p = __fmul_rn(xc, p);
    float q = fmaf(x2, 1.19825839466702e-06f, 1.18534705686654e-04f);
    q = fmaf(x2, q, 2.26843463243900e-03f);
    q = fmaf(x2, q, 4.89352518554385e-03f);
    return (ax < 0.0004f) ? x : __fdiv_rn(p, q);
}
__device__ __forceinline__ float xla_sigmoidf(float x) {
    const float t = xla_tanhf(__fmul_rn(0.5f, x));
    return __fadd_rn(__fmul_rn(0.5f, t), 0.5f);
}

// ---------------------------------------------------------------------------
// Identical fused-fma chain step as the passing kernel (bit-exact order).
// ---------------------------------------------------------------------------
__device__ __forceinline__ void fma_step(float h, unsigned addr,
                                         unsigned long long& a0,
                                         unsigned long long& a1,
                                         unsigned long long& a2) {
    asm("{\n\t"
        ".reg .b64 hd, w0, w1, w2;\n\t"
        "mov.b64 hd, {%3, %3};\n\t"
        "ld.shared.b64 w0, [%4];\n\t"
        "ld.shared.b64 w1, [%4+8];\n\t"
        "ld.shared.b64 w2, [%4+16];\n\t"
        "fma.rn.f32x2 %0, hd, w0, %0;\n\t"
        "fma.rn.f32x2 %1, hd, w1, %1;\n\t"
        "fma.rn.f32x2 %2, hd, w2, %2;\n\t"
        "}"
        : "+l"(a0), "+l"(a1), "+l"(a2)
        : "f"(h), "r"(addr));
}

// ---------------------------------------------------------------------------
// Kernel 1: per-chunk partial logits. 2 threads/token (jh split), W k-major
// [k][12] in smem (broadcast reads), hidden staged via 16B cp.async into
// plane-major tiles, 4-stage pipeline, 8 warps/block for latency hiding.
// Ascending-k fma chain within the chunk is unchanged -> bit-exact.
// ---------------------------------------------------------------------------
__global__ __launch_bounds__(TPB, 1)
void logits_kernel(const float* __restrict__ hidden,
                   const float* __restrict__ W) {
    extern __shared__ float sm[];
    const int tid   = threadIdx.x;
    const int chunk = blockIdx.y;
    const int kc    = chunk * KC;
    const int tok0  = blockIdx.x * TOKB;
    const unsigned sb = (unsigned)__cvta_generic_to_shared(sm);
    const unsigned tb = sb + W_BYTES;

#define STAGE(T) do {                                                        \
    const int _t = (T);                                                      \
    const unsigned dst0 = tb + (unsigned)(_t & (NSTAGE - 1)) * TILE_BYTES;   \
    const float* src0 = hidden + (size_t)tok0 * HDIM + kc + _t * HT;         \
    _Pragma("unroll")                                                        \
    for (int r = 0; r < 4; ++r) {                                            \
        const int s = tid + r * TPB;                                         \
        const int tok = s >> 3, p = s & 7;                                   \
        const float* src = src0 + (size_t)tok * HDIM + p * 4;                \
        const unsigned dst = dst0 + p * (TOKB * 16) + tok * 16;              \
        asm volatile("cp.async.ca.shared.global [%0], [%1], 16;"             \
                     :: "r"(dst), "l"(src));                                 \
    }                                                                        \
    asm volatile("cp.async.commit_group;");                                  \
} while (0)

    STAGE(0); STAGE(1); STAGE(2);

    // W preload: sm[k*12 + j] = W[j][kc+k], coalesced global reads.
    for (int i = tid; i < KC * 12; i += TPB) {
        const int j = i >> 11;                // 0..11
        const int k = i & (KC - 1);
        sm[k * 12 + j] = W[(size_t)j * HDIM + kc + k];
    }

    const int jh = tid & 1;                   // which 6 outputs
    const int lt = tid >> 1;                  // local token 0..127
    const unsigned wb   = sb + jh * 24;       // W base, +48B per k
    const unsigned hrow = tb + lt * 16;

    unsigned long long a0 = 0ull, a1 = 0ull, a2 = 0ull;

    for (int t = 0; t < NT; ++t) {
        if (t + 3 < NT) {
            STAGE(t + 3);
            asm volatile("cp.async.wait_group 3;");
        } else {
            const int rem = NT - 1 - t;
            if (rem == 2)      asm volatile("cp.async.wait_group 2;");
            else if (rem == 1) asm volatile("cp.async.wait_group 1;");
            else               asm volatile("cp.async.wait_group 0;");
        }
        __syncthreads();

        const unsigned tbt = (unsigned)(t & (NSTAGE - 1)) * TILE_BYTES;
        unsigned wk = wb + (unsigned)(t * HT) * 48;
#pragma unroll
        for (int p = 0; p < 8; ++p) {
            float4 h;
            asm("ld.shared.v4.f32 {%0,%1,%2,%3}, [%4];"
                : "=f"(h.x), "=f"(h.y), "=f"(h.z), "=f"(h.w)
                : "r"(hrow + tbt + p * (TOKB * 16)));
            fma_step(h.x, wk,       a0, a1, a2);
            fma_step(h.y, wk + 48,  a0, a1, a2);
            fma_step(h.z, wk + 96,  a0, a1, a2);
            fma_step(h.w, wk + 144, a0, a1, a2);
            wk += 192;
        }
        __syncthreads();
    }
#undef STAGE

    const int gt = tok0 + lt;
    float2* pd = (float2*)&g_part[chunk][gt][jh * 6];
    pd[0] = *(float2*)&a0;
    pd[1] = *(float2*)&a1;
    pd[2] = *(float2*)&a2;
}

// ---------------------------------------------------------------------------
// Kernel 2: per-token routing epilogue, one warp per token (proven, 20us).
// Folds chunk partials ((0+p0)+p1)+b — exact passing rounding sequence.
// ---------------------------------------------------------------------------
__device__ __forceinline__ unsigned int ford(float v) {
    unsigned int u = __float_as_uint(v);
    return (u & 0x80000000u) ? ~u : (u | 0x80000000u);
}

__global__ __launch_bounds__(256, 8)
void route_kernel(const float* __restrict__ b, float* __restrict__ out) {
    const int lane  = threadIdx.x & 31;
    const int token = blockIdx.x * (blockDim.x >> 5) + (threadIdx.x >> 5);
    if (token >= NTOK) return;

    float lg = 0.f;
    if (lane < NOUT) {
        const float p0 = g_part[0][token][lane];
        const float p1 = g_part[1][token][lane];
        lg = __fadd_rn(__fadd_rn(__fadd_rn(0.0f, p0), p1), b[lane]);
    }
    float L[NOUT];
#pragma unroll
    for (int i = 0; i < NOUT; ++i) L[i] = __shfl_sync(0xffffffffu, lg, i);

    // anchor softmax over L[2], L[5], L[8], L[11]
    float pi[NANCH];
    {
        const float m = fmaxf(fmaxf(L[2], L[5]), fmaxf(L[8], L[11]));
        const float e0 = __nv_expf(__fadd_rn(L[2], -m));
        const float e1 = __nv_expf(__fadd_rn(L[5], -m));
        const float e2 = __nv_expf(__fadd_rn(L[8], -m));
        const float e3 = __nv_expf(__fadd_rn(L[11], -m));
        const float s = __fadd_rn(__fadd_rn(__fadd_rn(e0, e1), e2), e3);
        pi[0] = __fdiv_rn(e0, s); pi[1] = __fdiv_rn(e1, s);
        pi[2] = __fdiv_rn(e2, s); pi[3] = __fdiv_rn(e3, s);
    }

    float v0 = 0.f, v1 = 0.f;   // my two cells: lane, lane+32

#pragma unroll
    for (int a = 0; a < NANCH; ++a) {
        float fr[2]; int ai[2];
#pragma unroll
        for (int d = 0; d < 2; ++d) {
            const float x = L[a * 3 + d];
            float u = xla_sigmoidf(x);
            u = fminf(fmaxf(u, 1e-6f), 1.0f - 1e-6f);
            float p = __fmul_rn(u, 7.0f);
            p = fminf(p, 7.0f - 1e-6f);
            p = fmaxf(p, 0.f);
            int aa = (int)floorf(p);
            aa = max(0, min(aa, 6));
            float f = __fadd_rn(p, -(float)aa);
            f = fminf(fmaxf(f, 1e-6f), 1.0f - 1e-6f);
            fr[d] = f; ai[d] = aa;
        }
        const float om0 = __fadd_rn(1.0f, -fr[0]);
        const float om1 = __fadd_rn(1.0f, -fr[1]);
        float w[4];
        w[0] = __fmul_rn(om0,   om1);
        w[1] = __fmul_rn(fr[0], om1);
        w[2] = __fmul_rn(om0,   fr[1]);
        w[3] = __fmul_rn(fr[0], fr[1]);
        const float ws = __fadd_rn(__fadd_rn(__fadd_rn(w[0], w[1]), w[2]), w[3]);
        const float denom = __fadd_rn(ws, 1e-9f);
#pragma unroll
        for (int t = 0; t < 4; ++t) {
            const int c0 = ai[0] + (t & 1);
            const int c1 = ai[1] + ((t >> 1) & 1);
            const int idx = c0 + (c1 << 3);
            const float wv = __fmul_rn(__fdiv_rn(w[t], denom), pi[a]);
            if (idx == lane)      v0 = __fadd_rn(v0, wv);
            if (idx == lane + 32) v1 = __fadd_rn(v1, wv);
        }
    }

    // normalize by grid sum (common denominator: cannot flip ranks)
    float s = __fadd_rn(v0, v1);
    s = __fadd_rn(s, __shfl_xor_sync(0xffffffffu, s, 16));
    s = __fadd_rn(s, __shfl_xor_sync(0xffffffffu, s, 8));
    s = __fadd_rn(s, __shfl_xor_sync(0xffffffffu, s, 4));
    s = __fadd_rn(s, __shfl_xor_sync(0xffffffffu, s, 2));
    s = __fadd_rn(s, __shfl_xor_sync(0xffffffffu, s, 1));
    const float dn = __fadd_rn(s, 1e-9f);
    v0 = __fdiv_rn(v0, dn);
    v1 = __fdiv_rn(v1, dn);

    float* out_idx = out + (size_t)token * KOUT;
    float* out_w   = out + (size_t)NTOK * KOUT + (size_t)token * KOUT;

    for (int r = 0; r < KOUT; ++r) {
        unsigned long long k0 =
            ((unsigned long long)ford(v0) << 32) | (unsigned int)(63 - lane);
        unsigned long long k1 =
            ((unsigned long long)ford(v1) << 32) | (unsigned int)(63 - (lane + 32));
        unsigned long long k = (k0 > k1) ? k0 : k1;
#pragma unroll
        for (int sft = 16; sft > 0; sft >>= 1) {
            unsigned long long o = __shfl_xor_sync(0xffffffffu, k, sft);
            if (o > k) k = o;
        }
        const int cell = 63 - (int)(k & 63ull);
        const unsigned int ou = (unsigned int)(k >> 32);
        const float val =
            __uint_as_float((ou & 0x80000000u) ? (ou ^ 0x80000000u) : ~ou);
        if (lane == 0) {
            out_idx[r] = (float)cell;
            out_w[r]   = val;
        }
        if (cell == lane)      v0 = -1.0f;
        if (cell == lane + 32) v1 = -1.0f;
    }
}

// ---------------------------------------------------------------------------
extern "C" void kernel_launch(void* const* d_in, const int* in_sizes, int n_in,
                              void* d_out, int out_size) {
    const float* hidden = nullptr;
    const float* W = nullptr;
    const float* b = nullptr;
    for (int i = 0; i < n_in; ++i) {
        if (in_sizes[i] == NTOK * HDIM)      hidden = (const float*)d_in[i];
        else if (in_sizes[i] == NOUT * HDIM) W = (const float*)d_in[i];
        else if (in_sizes[i] == NOUT)        b = (const float*)d_in[i];
    }
    (void)out_size;

    cudaFuncSetAttribute(logits_kernel,
                         cudaFuncAttributeMaxDynamicSharedMemorySize, SMEM_TOTAL);
    dim3 grid(NTOK / TOKB, 2);
    logits_kernel<<<grid, TPB, SMEM_TOTAL>>>(hidden, W);
    route_kernel<<<NTOK / 8, 256>>>(b, (float*)d_out);
}

// round 13
// speedup vs baseline: 1.8098x; 1.3442x over previous
#include <cuda_runtime.h>
#include <math.h>

#define NTOK 8192
#define HDIM 4096
#define NOUT 12       // M_ANCH * (D+1)
#define NANCH 4
#define KOUT 16

// GEMM decomposition (rounding-order-mandated): 2 contiguous chunks of 2048.
#define KC 2048
#define HT 32                        // k per tile
#define NT (KC / HT)                 // 64 tiles
#define TOKB 128                     // tokens per block
#define TPB 256                      // 2 threads per token
#define NSTAGE 6
#define ROWB 144                     // bytes per token row (128 data + 16 pad)
#define W_BYTES (KC * 48)            // [k][12] 48B rows = 98304
#define TILE_BYTES (TOKB * ROWB)     // 18432
#define SMEM_TOTAL (W_BYTES + NSTAGE * TILE_BYTES)   // 208896

extern "C" __device__ float __nv_expf(float);

// chunk partial sums: g_part[chunk][token][j]
__device__ float g_part[2][NTOK][NOUT];

// ---------------------------------------------------------------------------
// XLA f32 tanh (EmitFastTanh), bit-exact — frozen since round 5.
// ---------------------------------------------------------------------------
__device__ __forceinline__ float xla_tanhf(float x) {
    const float plus_clamp = 7.90531110763549805f;
    const float ax = fabsf(x);
    const float xc = fmaxf(fminf(x, plus_clamp), -plus_clamp);
    const float x2 = __fmul_rn(xc, xc);
    float p = fmaf(x2, -2.76076847742355e-16f, 2.00018790482477e-13f);
    p = fmaf(x2, p, -8.60467152213735e-11f);
    p = fmaf(x2, p, 5.12229709037114e-08f);
    p = fmaf(x2, p, 1.48572235717979e-05f);
    p = fmaf(x2, p, 6.37261928875436e-04f);
    p = fmaf(x2, p, 4.89352455891786e-03f);
    p = __fmul_rn(xc, p);
    float q = fmaf(x2, 1.19825839466702e-06f, 1.18534705686654e-04f);
    q = fmaf(x2, q, 2.26843463243900e-03f);
    q = fmaf(x2, q, 4.89352518554385e-03f);
    return (ax < 0.0004f) ? x : __fdiv_rn(p, q);
}
__device__ __forceinline__ float xla_sigmoidf(float x) {
    const float t = xla_tanhf(__fmul_rn(0.5f, x));
    return __fadd_rn(__fmul_rn(0.5f, t), 0.5f);
}

// ---------------------------------------------------------------------------
// Identical fused-fma chain step as the passing kernel (bit-exact order).
// ---------------------------------------------------------------------------
__device__ __forceinline__ void fma_step(float h, unsigned addr,
                                         unsigned long long& a0,
                                         unsigned long long& a1,
                                         unsigned long long& a2) {
    asm("{\n\t"
        ".reg .b64 hd, w0, w1, w2;\n\t"
        "mov.b64 hd, {%3, %3};\n\t"
        "ld.shared.b64 w0, [%4];\n\t"
        "ld.shared.b64 w1, [%4+8];\n\t"
        "ld.shared.b64 w2, [%4+16];\n\t"
        "fma.rn.f32x2 %0, hd, w0, %0;\n\t"
        "fma.rn.f32x2 %1, hd, w1, %1;\n\t"
        "fma.rn.f32x2 %2, hd, w2, %2;\n\t"
        "}"
        : "+l"(a0), "+l"(a1), "+l"(a2)
        : "f"(h), "r"(addr));
}

// ---------------------------------------------------------------------------
// Kernel 1: per-chunk partial logits. 2 threads/token (jh split), W k-major
// [k][12] in smem (broadcast reads). Hidden staged via 16B cp.async into
// padded row-major tiles (ROWB=144 -> conflict-free STS AND LDS), 6-stage
// pipeline (slack >> DRAM latency). Ascending-k fma chain unchanged.
// ---------------------------------------------------------------------------
__global__ __launch_bounds__(TPB, 1)
void logits_kernel(const float* __restrict__ hidden,
                   const float* __restrict__ W) {
    extern __shared__ float sm[];
    const int tid   = threadIdx.x;
    const int chunk = blockIdx.y;
    const int kc    = chunk * KC;
    const int tok0  = blockIdx.x * TOKB;
    const unsigned sb = (unsigned)__cvta_generic_to_shared(sm);
    const unsigned tb = sb + W_BYTES;

#define STAGE(T, SLOT) do {                                                  \
    const int _t = (T);                                                      \
    const unsigned dst0 = tb + (unsigned)(SLOT) * TILE_BYTES;                \
    const float* src0 = hidden + (size_t)tok0 * HDIM + kc + _t * HT;         \
    _Pragma("unroll")                                                        \
    for (int r = 0; r < 4; ++r) {                                            \
        const int s = tid + r * TPB;                                         \
        const int tok = s >> 3, p = s & 7;                                   \
        const float* src = src0 + (size_t)tok * HDIM + p * 4;                \
        const unsigned dst = dst0 + tok * ROWB + p * 16;                     \
        asm volatile("cp.async.ca.shared.global [%0], [%1], 16;"             \
                     :: "r"(dst), "l"(src));                                 \
    }                                                                        \
    asm volatile("cp.async.commit_group;");                                  \
} while (0)

    STAGE(0, 0); STAGE(1, 1); STAGE(2, 2); STAGE(3, 3); STAGE(4, 4);

    // W preload: sm[k*12 + j] = W[j][kc+k], coalesced global reads.
    for (int i = tid; i < KC * 12; i += TPB) {
        const int j = i >> 11;                // 0..11
        const int k = i & (KC - 1);
        sm[k * 12 + j] = W[(size_t)j * HDIM + kc + k];
    }

    const int jh = tid & 1;                   // which 6 outputs
    const int lt = tid >> 1;                  // local token 0..127
    const unsigned wb   = sb + jh * 24;       // W base, +48B per k
    const unsigned hrow = tb + lt * ROWB;

    unsigned long long a0 = 0ull, a1 = 0ull, a2 = 0ull;

    int slot = 0;       // slot of tile t
    int nslot = 5;      // slot where tile t+5 goes
    for (int t = 0; t < NT; ++t) {
        if (t + 5 < NT) {
            STAGE(t + 5, nslot);
            asm volatile("cp.async.wait_group 5;");
        } else {
            switch (NT - 1 - t) {
            case 4: asm volatile("cp.async.wait_group 4;"); break;
            case 3: asm volatile("cp.async.wait_group 3;"); break;
            case 2: asm volatile("cp.async.wait_group 2;"); break;
            case 1: asm volatile("cp.async.wait_group 1;"); break;
            default: asm volatile("cp.async.wait_group 0;"); break;
            }
        }
        __syncthreads();

        const unsigned hbase = hrow + (unsigned)slot * TILE_BYTES;
        unsigned wk = wb + (unsigned)(t * HT) * 48;
#pragma unroll
        for (int p = 0; p < 8; ++p) {
            float4 h;
            asm("ld.shared.v4.f32 {%0,%1,%2,%3}, [%4];"
                : "=f"(h.x), "=f"(h.y), "=f"(h.z), "=f"(h.w)
                : "r"(hbase + p * 16));
            fma_step(h.x, wk,       a0, a1, a2);
            fma_step(h.y, wk + 48,  a0, a1, a2);
            fma_step(h.z, wk + 96,  a0, a1, a2);
            fma_step(h.w, wk + 144, a0, a1, a2);
            wk += 192;
        }
        __syncthreads();

        if (++slot == NSTAGE) slot = 0;
        if (++nslot == NSTAGE) nslot = 0;
    }
#undef STAGE

    const int gt = tok0 + lt;
    float2* pd = (float2*)&g_part[chunk][gt][jh * 6];
    pd[0] = *(float2*)&a0;
    pd[1] = *(float2*)&a1;
    pd[2] = *(float2*)&a2;
}

// ---------------------------------------------------------------------------
// Kernel 2: per-token routing epilogue, one warp per token (proven, 20us).
// Folds chunk partials ((0+p0)+p1)+b — exact passing rounding sequence.
// ---------------------------------------------------------------------------
__device__ __forceinline__ unsigned int ford(float v) {
    unsigned int u = __float_as_uint(v);
    return (u & 0x80000000u) ? ~u : (u | 0x80000000u);
}

__global__ __launch_bounds__(256, 8)
void route_kernel(const float* __restrict__ b, float* __restrict__ out) {
    const int lane  = threadIdx.x & 31;
    const int token = blockIdx.x * (blockDim.x >> 5) + (threadIdx.x >> 5);
    if (token >= NTOK) return;

    float lg = 0.f;
    if (lane < NOUT) {
        const float p0 = g_part[0][token][lane];
        const float p1 = g_part[1][token][lane];
        lg = __fadd_rn(__fadd_rn(__fadd_rn(0.0f, p0), p1), b[lane]);
    }
    float L[NOUT];
#pragma unroll
    for (int i = 0; i < NOUT; ++i) L[i] = __shfl_sync(0xffffffffu, lg, i);

    // anchor softmax over L[2], L[5], L[8], L[11]
    float pi[NANCH];
    {
        const float m = fmaxf(fmaxf(L[2], L[5]), fmaxf(L[8], L[11]));
        const float e0 = __nv_expf(__fadd_rn(L[2], -m));
        const float e1 = __nv_expf(__fadd_rn(L[5], -m));
        const float e2 = __nv_expf(__fadd_rn(L[8], -m));
        const float e3 = __nv_expf(__fadd_rn(L[11], -m));
        const float s = __fadd_rn(__fadd_rn(__fadd_rn(e0, e1), e2), e3);
        pi[0] = __fdiv_rn(e0, s); pi[1] = __fdiv_rn(e1, s);
        pi[2] = __fdiv_rn(e2, s); pi[3] = __fdiv_rn(e3, s);
    }

    float v0 = 0.f, v1 = 0.f;   // my two cells: lane, lane+32

#pragma unroll
    for (int a = 0; a < NANCH; ++a) {
        float fr[2]; int ai[2];
#pragma unroll
        for (int d = 0; d < 2; ++d) {
            const float x = L[a * 3 + d];
            float u = xla_sigmoidf(x);
            u = fminf(fmaxf(u, 1e-6f), 1.0f - 1e-6f);
            float p = __fmul_rn(u, 7.0f);
            p = fminf(p, 7.0f - 1e-6f);
            p = fmaxf(p, 0.f);
            int aa = (int)floorf(p);
            aa = max(0, min(aa, 6));
            float f = __fadd_rn(p, -(float)aa);
            f = fminf(fmaxf(f, 1e-6f), 1.0f - 1e-6f);
            fr[d] = f; ai[d] = aa;
        }
        const float om0 = __fadd_rn(1.0f, -fr[0]);
        const float om1 = __fadd_rn(1.0f, -fr[1]);
        float w[4];
        w[0] = __fmul_rn(om0,   om1);
        w[1] = __fmul_rn(fr[0], om1);
        w[2] = __fmul_rn(om0,   fr[1]);
        w[3] = __fmul_rn(fr[0], fr[1]);
        const float ws = __fadd_rn(__fadd_rn(__fadd_rn(w[0], w[1]), w[2]), w[3]);
        const float denom = __fadd_rn(ws, 1e-9f);
#pragma unroll
        for (int t = 0; t < 4; ++t) {
            const int c0 = ai[0] + (t & 1);
            const int c1 = ai[1] + ((t >> 1) & 1);
            const int idx = c0 + (c1 << 3);
            const float wv = __fmul_rn(__fdiv_rn(w[t], denom), pi[a]);
            if (idx == lane)      v0 = __fadd_rn(v0, wv);
            if (idx == lane + 32) v1 = __fadd_rn(v1, wv);
        }
    }

    // normalize by grid sum (common denominator: cannot flip ranks)
    float s = __fadd_rn(v0, v1);
    s = __fadd_rn(s, __shfl_xor_sync(0xffffffffu, s, 16));
    s = __fadd_rn(s, __shfl_xor_sync(0xffffffffu, s, 8));
    s = __fadd_rn(s, __shfl_xor_sync(0xffffffffu, s, 4));
    s = __fadd_rn(s, __shfl_xor_sync(0xffffffffu, s, 2));
    s = __fadd_rn(s, __shfl_xor_sync(0xffffffffu, s, 1));
    const float dn = __fadd_rn(s, 1e-9f);
    v0 = __fdiv_rn(v0, dn);
    v1 = __fdiv_rn(v1, dn);

    float* out_idx = out + (size_t)token * KOUT;
    float* out_w   = out + (size_t)NTOK * KOUT + (size_t)token * KOUT;

    for (int r = 0; r < KOUT; ++r) {
        unsigned long long k0 =
            ((unsigned long long)ford(v0) << 32) | (unsigned int)(63 - lane);
        unsigned long long k1 =
            ((unsigned long long)ford(v1) << 32) | (unsigned int)(63 - (lane + 32));
        unsigned long long k = (k0 > k1) ? k0 : k1;
#pragma unroll
        for (int sft = 16; sft > 0; sft >>= 1) {
            unsigned long long o = __shfl_xor_sync(0xffffffffu, k, sft);
            if (o > k) k = o;
        }
        const int cell = 63 - (int)(k & 63ull);
        const unsigned int ou = (unsigned int)(k >> 32);
        const float val =
            __uint_as_float((ou & 0x80000000u) ? (ou ^ 0x80000000u) : ~ou);
        if (lane == 0) {
            out_idx[r] = (float)cell;
            out_w[r]   = val;
        }
        if (cell == lane)      v0 = -1.0f;
        if (cell == lane + 32) v1 = -1.0f;
    }
}

// ---------------------------------------------------------------------------
extern "C" void kernel_launch(void* const* d_in, const int* in_sizes, int n_in,
                              void* d_out, int out_size) {
    const float* hidden = nullptr;
    const float* W = nullptr;
    const float* b = nullptr;
    for (int i = 0; i < n_in; ++i) {
        if (in_sizes[i] == NTOK * HDIM)      hidden = (const float*)d_in[i];
        else if (in_sizes[i] == NOUT * HDIM) W = (const float*)d_in[i];
        else if (in_sizes[i] == NOUT)        b = (const float*)d_in[i];
    }
    (void)out_size;

    cudaFuncSetAttribute(logits_kernel,
                         cudaFuncAttributeMaxDynamicSharedMemorySize, SMEM_TOTAL);
    dim3 grid(NTOK / TOKB, 2);
    logits_kernel<<<grid, TPB, SMEM_TOTAL>>>(hidden, W);
    route_kernel<<<NTOK / 8, 256>>>(b, (float*)d_out);
}